// round 7
// baseline (speedup 1.0000x reference)
#include <cuda_runtime.h>

// ---------------------------------------------------------------------------
// Soft-silhouette render loss.
//   K0: project vertices + bake per-edge line coefficients (pre-scaled by
//       -log2e * sgn / (sigma * elen)) so the inner loop is pure FMA + EX2.
//   K1: per (pixel-block, face-group): accumulate log2(1 - inside + eps)
//       with a warp-vote cull for far faces (contribution == eps constant).
//   K2: image = 1 - exp2(sum), squared diff vs ref, block partial sums.
//   K3: reduce partials, apply (1 + relu(6 - |cam|)).
// ---------------------------------------------------------------------------

#define HH 192
#define WW 192
#define NPIX (HH * WW)            // 36864
#define NV 1024
#define NF 2048
#define FACE_GROUPS 4
#define FPG (NF / FACE_GROUPS)    // 512
#define PIX_BLOCKS (NPIX / 256)   // 144

#define LOG2E_F 1.4426950408889634f
#define SIGMA_F 0.01f
#define RATIO_F 0.57735026918962576f   // tan(30 deg)
#define SKIP_THR 34.0f
// lg2(fp32(1.0f + 1e-7f)) = lg2(1 + 2^-23) : matches reference f32 rounding
#define SKIP_CONST 1.7198266e-7f

__device__ float4 g_coef[NF * 3];
__device__ float  g_lm[FACE_GROUPS][NPIX];
__device__ float  g_partial[PIX_BLOCKS];

static __device__ __forceinline__ float ex2f(float x) {
    float r; asm("ex2.approx.ftz.f32 %0, %1;" : "=f"(r) : "f"(x)); return r;
}
static __device__ __forceinline__ float lg2af(float x) {
    float r; asm("lg2.approx.ftz.f32 %0, %1;" : "=f"(r) : "f"(x)); return r;
}
static __device__ __forceinline__ float rcpaf(float x) {
    float r; asm("rcp.approx.ftz.f32 %0, %1;" : "=f"(r) : "f"(x)); return r;
}

// ---------------------------------------------------------------------------
// K0: camera transform, vertex projection, per-face edge coefficients
// ---------------------------------------------------------------------------
__global__ void __launch_bounds__(1024) setup_kernel(
    const float* __restrict__ verts,
    const int*   __restrict__ faces,
    const float* __restrict__ cam)
{
    __shared__ float2 sP[NV];
    int tid = threadIdx.x;

    float cx = cam[0], cy = cam[1], cz = cam[2];
    // z_axis = normalize(-eye)
    float n  = fmaxf(sqrtf(cx * cx + cy * cy + cz * cz), 1e-8f);
    float zx = -cx / n, zy = -cy / n, zz = -cz / n;
    // x_axis = normalize(cross([0,1,0], z)) = normalize((zz, 0, -zx))
    float xl = fmaxf(sqrtf(zz * zz + zx * zx), 1e-8f);
    float xx = zz / xl, xz = -zx / xl;     // x_axis.y == 0
    // y_axis = cross(z, x)
    float yx = zy * xz;
    float yy = zz * xx - zx * xz;
    float yz = -zy * xx;

    // project vertex 'tid'
    {
        float vx = verts[3 * tid + 0] - cx;
        float vy = verts[3 * tid + 1] - cy;
        float vz = verts[3 * tid + 2] - cz;
        float pxc = vx * xx + vz * xz;
        float pyc = vx * yx + vy * yy + vz * yz;
        float pzc = vx * zx + vy * zy + vz * zz;
        pzc = fmaxf(pzc, 1e-5f);
        float inv = 1.0f / (pzc * RATIO_F);
        sP[tid] = make_float2(pxc * inv, pyc * inv);
    }
    __syncthreads();

    for (int f = tid; f < NF; f += 1024) {
        int i0 = faces[3 * f + 0];
        int i1 = faces[3 * f + 1];
        int i2 = faces[3 * f + 2];
        float2 p0 = sP[i0], p1 = sP[i1], p2 = sP[i2];

        float exv[3], eyv[3], axv[3], ayv[3];
        exv[0] = p1.x - p0.x; eyv[0] = p1.y - p0.y; axv[0] = p0.x; ayv[0] = p0.y;
        exv[1] = p2.x - p1.x; eyv[1] = p2.y - p1.y; axv[1] = p1.x; ayv[1] = p1.y;
        exv[2] = p0.x - p2.x; eyv[2] = p0.y - p2.y; axv[2] = p2.x; ayv[2] = p2.y;

        float area2 = (p1.x - p0.x) * (p2.y - p0.y) - (p1.y - p0.y) * (p2.x - p0.x);
        float sgn = (area2 >= 0.0f) ? 1.0f : -1.0f;

        #pragma unroll
        for (int i = 0; i < 3; i++) {
            float c    = eyv[i] * axv[i] - exv[i] * ayv[i];
            float elen = fmaxf(sqrtf(exv[i] * exv[i] + eyv[i] * eyv[i]), 1e-8f);
            // a_i = -(d_i / sigma) * log2e ; d_i = (ex*py - ey*px + c) * sgn/elen
            float K = sgn * (LOG2E_F / SIGMA_F) / elen;
            // layout: .x -> * py, .y -> * px, .z -> const
            g_coef[3 * f + i] = make_float4(-K * exv[i], K * eyv[i], -K * c, 0.0f);
        }
    }
}

// ---------------------------------------------------------------------------
// K1: main rasterization loop (MUFU-bound); warp-vote cull for far faces
// ---------------------------------------------------------------------------
__global__ void __launch_bounds__(256) face_kernel()
{
    __shared__ float4 sC[FPG * 3];   // 24 KB
    const float4* src = g_coef + blockIdx.y * (FPG * 3);
    for (int i = threadIdx.x; i < FPG * 3; i += 256) sC[i] = src[i];
    __syncthreads();

    int p = blockIdx.x * 256 + threadIdx.x;
    int h = p / WW;
    int w = p - h * WW;
    float px = (w + 0.5f) * (2.0f / WW) - 1.0f;
    float py = 1.0f - (h + 0.5f) * (2.0f / HH);

    float acc = 0.0f;
    int nskip = 0;

    #pragma unroll 2
    for (int f = 0; f < FPG; ++f) {
        float4 c0 = sC[3 * f + 0];
        float4 c1 = sC[3 * f + 1];
        float4 c2 = sC[3 * f + 2];
        float a0 = fmaf(c0.y, px, fmaf(c0.x, py, c0.z));
        float a1 = fmaf(c1.y, px, fmaf(c1.x, py, c1.z));
        float a2 = fmaf(c2.y, px, fmaf(c2.x, py, c2.z));

        // If every lane has some a_i > 34, then inside < 2^-34 for the whole
        // warp: contribution is exactly lg2(1 + eps) -> count and skip MUFUs.
        float m = fmaxf(fmaxf(a0, a1), a2);
        if (__all_sync(0xffffffffu, m > SKIP_THR)) { nskip++; continue; }

        float e0 = ex2f(a0);       // = exp(-d0/sigma)
        float e1 = ex2f(a1);
        float e2 = ex2f(a2);
        // inside = prod sigmoid = 1 / ((1+e0)(1+e1)(1+e2))
        float P   = (1.0f + e0) * ((1.0f + e1) * (1.0f + e2));
        float arg = (1.0f - rcpaf(P)) + 1e-7f;   // same rounding as reference
        acc += lg2af(arg);
    }

    g_lm[blockIdx.y][p] = fmaf((float)nskip, SKIP_CONST, acc);
}

// ---------------------------------------------------------------------------
// K2: image + squared-diff partial sums per pixel block
// ---------------------------------------------------------------------------
__global__ void __launch_bounds__(256) image_kernel(const float* __restrict__ ref)
{
    int p = blockIdx.x * 256 + threadIdx.x;
    float lm = g_lm[0][p] + g_lm[1][p] + g_lm[2][p] + g_lm[3][p];
    float img = 1.0f - ex2f(lm);       // exp(log_miss) with log2 accumulation
    float d = ref[p] - img;
    float v = d * d;

    #pragma unroll
    for (int off = 16; off; off >>= 1)
        v += __shfl_xor_sync(0xffffffffu, v, off);

    __shared__ float ws[8];
    if ((threadIdx.x & 31) == 0) ws[threadIdx.x >> 5] = v;
    __syncthreads();
    if (threadIdx.x == 0) {
        float s = 0.0f;
        #pragma unroll
        for (int i = 0; i < 8; i++) s += ws[i];
        g_partial[blockIdx.x] = s;
    }
}

// ---------------------------------------------------------------------------
// K3: final reduction + distance penalty
// ---------------------------------------------------------------------------
__global__ void __launch_bounds__(256) loss_kernel(const float* __restrict__ cam,
                                                   float* __restrict__ out)
{
    __shared__ float ws[8];
    int tid = threadIdx.x;
    float v = (tid < PIX_BLOCKS) ? g_partial[tid] : 0.0f;

    #pragma unroll
    for (int off = 16; off; off >>= 1)
        v += __shfl_xor_sync(0xffffffffu, v, off);
    if ((tid & 31) == 0) ws[tid >> 5] = v;
    __syncthreads();

    if (tid == 0) {
        float s = 0.0f;
        #pragma unroll
        for (int i = 0; i < 8; i++) s += ws[i];
        float dx = cam[0], dy = cam[1], dz = cam[2];
        float dist = sqrtf(dx * dx + dy * dy + dz * dz);
        float pen = fmaxf(6.0f - dist, 0.0f);
        out[0] = s * (1.0f + pen);
    }
}

// ---------------------------------------------------------------------------
extern "C" void kernel_launch(void* const* d_in, const int* in_sizes, int n_in,
                              void* d_out, int out_size)
{
    const float* verts = (const float*)d_in[0];
    const int*   faces = (const int*)d_in[1];
    const float* ref   = (const float*)d_in[2];
    const float* cam   = (const float*)d_in[3];
    float* out = (float*)d_out;
    (void)in_sizes; (void)n_in; (void)out_size;

    setup_kernel<<<1, 1024>>>(verts, faces, cam);
    dim3 grid(PIX_BLOCKS, FACE_GROUPS);
    face_kernel<<<grid, 256>>>();
    image_kernel<<<PIX_BLOCKS, 256>>>(ref);
    loss_kernel<<<1, 256>>>(cam, out);
}

// round 8
// speedup vs baseline: 1.1248x; 1.1248x over previous
#include <cuda_runtime.h>

// ---------------------------------------------------------------------------
// Soft-silhouette render loss, tile-binned.
//   K0: project vertices + bake per-edge line coefficients (pre-scaled by
//       -log2e * sgn / (sigma * elen)) so the inner loop is pure FMA + EX2.
//   Kb: per 16x16-pixel tile, conservative cull test per face (affine edge
//       functions -> corner bound); compact surviving faces' coefs per tile.
//   K1: per (tile, face-group): accumulate log2(1 - inside + eps) over the
//       tile's surviving faces only; tile-culled faces contribute the exact
//       constant lg2(1+2^-23); per-warp vote handles warp-level culls.
//   K2: image = 1 - exp2(sum), squared diff vs ref, block partial sums.
//   K3: reduce partials, apply (1 + relu(6 - |cam|)).
// ---------------------------------------------------------------------------

#define HH 192
#define WW 192
#define NPIX (HH * WW)            // 36864
#define NV 1024
#define NF 2048
#define PIX_BLOCKS (NPIX / 256)   // 144

#define TILE 16
#define TX (WW / TILE)            // 12
#define NTILE (TX * TX)           // 144
#define G 4                       // face groups per tile
#define CAP (NF / G)              // 512: max faces per group chunk

#define LOG2E_F 1.4426950408889634f
#define SIGMA_F 0.01f
#define RATIO_F 0.57735026918962576f   // tan(30 deg)
// Exactness needs inside < 2^-25 (then 1-inside rounds to 1.0f and the
// +1e-7f rounds to 1+2^-23). amax > 26.5 guarantees inside < 2^-26.
#define SKIP_THR 26.5f
// lg2(fp32(1.0f + 1e-7f)) = lg2(1 + 2^-23)
#define SKIP_CONST 1.7198266e-7f

__device__ float4 g_coef[NF * 3];
__device__ float4 g_tcoef[NTILE][NF * 3];   // compacted per-tile coef lists
__device__ int    g_tcnt[NTILE];
__device__ float  g_lm[G][NPIX];
__device__ float  g_partial[PIX_BLOCKS];

static __device__ __forceinline__ float ex2f(float x) {
    float r; asm("ex2.approx.ftz.f32 %0, %1;" : "=f"(r) : "f"(x)); return r;
}
static __device__ __forceinline__ float lg2af(float x) {
    float r; asm("lg2.approx.ftz.f32 %0, %1;" : "=f"(r) : "f"(x)); return r;
}
static __device__ __forceinline__ float rcpaf(float x) {
    float r; asm("rcp.approx.ftz.f32 %0, %1;" : "=f"(r) : "f"(x)); return r;
}

// ---------------------------------------------------------------------------
// K0: camera transform, vertex projection, per-face edge coefficients
// ---------------------------------------------------------------------------
__global__ void __launch_bounds__(1024) setup_kernel(
    const float* __restrict__ verts,
    const int*   __restrict__ faces,
    const float* __restrict__ cam)
{
    __shared__ float2 sP[NV];
    int tid = threadIdx.x;

    float cx = cam[0], cy = cam[1], cz = cam[2];
    float n  = fmaxf(sqrtf(cx * cx + cy * cy + cz * cz), 1e-8f);
    float zx = -cx / n, zy = -cy / n, zz = -cz / n;
    float xl = fmaxf(sqrtf(zz * zz + zx * zx), 1e-8f);
    float xx = zz / xl, xz = -zx / xl;     // x_axis.y == 0
    float yx = zy * xz;
    float yy = zz * xx - zx * xz;
    float yz = -zy * xx;

    {
        float vx = verts[3 * tid + 0] - cx;
        float vy = verts[3 * tid + 1] - cy;
        float vz = verts[3 * tid + 2] - cz;
        float pxc = vx * xx + vz * xz;
        float pyc = vx * yx + vy * yy + vz * yz;
        float pzc = vx * zx + vy * zy + vz * zz;
        pzc = fmaxf(pzc, 1e-5f);
        float inv = 1.0f / (pzc * RATIO_F);
        sP[tid] = make_float2(pxc * inv, pyc * inv);
    }
    __syncthreads();

    for (int f = tid; f < NF; f += 1024) {
        int i0 = faces[3 * f + 0];
        int i1 = faces[3 * f + 1];
        int i2 = faces[3 * f + 2];
        float2 p0 = sP[i0], p1 = sP[i1], p2 = sP[i2];

        float exv[3], eyv[3], axv[3], ayv[3];
        exv[0] = p1.x - p0.x; eyv[0] = p1.y - p0.y; axv[0] = p0.x; ayv[0] = p0.y;
        exv[1] = p2.x - p1.x; eyv[1] = p2.y - p1.y; axv[1] = p1.x; ayv[1] = p1.y;
        exv[2] = p0.x - p2.x; eyv[2] = p0.y - p2.y; axv[2] = p2.x; ayv[2] = p2.y;

        float area2 = (p1.x - p0.x) * (p2.y - p0.y) - (p1.y - p0.y) * (p2.x - p0.x);
        float sgn = (area2 >= 0.0f) ? 1.0f : -1.0f;

        #pragma unroll
        for (int i = 0; i < 3; i++) {
            float c    = eyv[i] * axv[i] - exv[i] * ayv[i];
            float elen = fmaxf(sqrtf(exv[i] * exv[i] + eyv[i] * eyv[i]), 1e-8f);
            float K = sgn * (LOG2E_F / SIGMA_F) / elen;
            // a_i(px,py) = x*py + y*px + z ; a = -(d_i/sigma)*log2e
            g_coef[3 * f + i] = make_float4(-K * exv[i], K * eyv[i], -K * c, 0.0f);
        }
    }
}

// ---------------------------------------------------------------------------
// Kb: per-tile conservative cull + ordered compaction of surviving coefs
// ---------------------------------------------------------------------------
__global__ void __launch_bounds__(256) bin_kernel()
{
    int tile = blockIdx.x;
    int tx = tile % TX, ty = tile / TX;
    // pixel centers: px = (w+0.5)/96 - 1 ; py = 1 - (h+0.5)/96
    float pxc = (float)(tx * TILE + 8) * (1.0f / 96.0f) - 1.0f;
    float pyc = 1.0f - (float)(ty * TILE + 8) * (1.0f / 96.0f);
    const float he = 7.5f / 96.0f;   // half-extent of pixel centers in a tile

    int t = threadIdx.x;
    bool keep[8];
    int cnt = 0;
    #pragma unroll
    for (int j = 0; j < 8; j++) {
        int f = t * 8 + j;
        bool cull = false;
        #pragma unroll
        for (int i = 0; i < 3; i++) {
            float4 c = __ldg(&g_coef[3 * f + i]);
            // min over tile of a_i = a_i(center) - (|A|+|B|)*he
            float amin = fmaf(c.x, pyc, fmaf(c.y, pxc, c.z))
                       - (fabsf(c.x) + fabsf(c.y)) * he;
            cull = cull || (amin > SKIP_THR);
        }
        keep[j] = !cull;
        cnt += keep[j] ? 1 : 0;
    }

    // block inclusive scan (Hillis-Steele) to get ordered write offsets
    __shared__ int sc[256];
    sc[t] = cnt;
    __syncthreads();
    #pragma unroll
    for (int off = 1; off < 256; off <<= 1) {
        int v = (t >= off) ? sc[t - off] : 0;
        __syncthreads();
        sc[t] += v;
        __syncthreads();
    }
    int base = sc[t] - cnt;
    if (t == 255) g_tcnt[tile] = sc[255];

    float4* dst = g_tcoef[tile];
    int o = base;
    #pragma unroll
    for (int j = 0; j < 8; j++) {
        if (keep[j]) {
            int f = t * 8 + j;
            dst[3 * o + 0] = __ldg(&g_coef[3 * f + 0]);
            dst[3 * o + 1] = __ldg(&g_coef[3 * f + 1]);
            dst[3 * o + 2] = __ldg(&g_coef[3 * f + 2]);
            o++;
        }
    }
}

// ---------------------------------------------------------------------------
// K1: main rasterization over the tile's surviving face list (MUFU-bound)
// ---------------------------------------------------------------------------
__global__ void __launch_bounds__(256) face_kernel()
{
    __shared__ float4 sC[CAP * 3];   // 24 KB
    int tile = blockIdx.x;
    int g    = blockIdx.y;

    int cnt = g_tcnt[tile];
    int beg = (cnt * g) / G;
    int end = (cnt * (g + 1)) / G;
    int nf  = end - beg;             // <= CAP always

    const float4* src = g_tcoef[tile] + 3 * beg;
    for (int i = threadIdx.x; i < 3 * nf; i += 256) sC[i] = src[i];
    __syncthreads();

    int tx = tile % TX, ty = tile / TX;
    int lw = threadIdx.x & (TILE - 1);
    int lh = threadIdx.x >> 4;
    int w = tx * TILE + lw;
    int h = ty * TILE + lh;
    float px = (w + 0.5f) * (1.0f / 96.0f) - 1.0f;
    float py = 1.0f - (h + 0.5f) * (1.0f / 96.0f);

    float acc = 0.0f;
    // tile-culled faces contribute exactly SKIP_CONST each (charge in group 0)
    int nskip = (g == 0) ? (NF - cnt) : 0;

    #pragma unroll 2
    for (int f = 0; f < nf; ++f) {
        float4 c0 = sC[3 * f + 0];
        float4 c1 = sC[3 * f + 1];
        float4 c2 = sC[3 * f + 2];
        float a0 = fmaf(c0.y, px, fmaf(c0.x, py, c0.z));
        float a1 = fmaf(c1.y, px, fmaf(c1.x, py, c1.z));
        float a2 = fmaf(c2.y, px, fmaf(c2.x, py, c2.z));

        float m = fmaxf(fmaxf(a0, a1), a2);
        if (__all_sync(0xffffffffu, m > SKIP_THR)) { nskip++; continue; }

        float e0 = ex2f(a0);       // = exp(-d0/sigma)
        float e1 = ex2f(a1);
        float e2 = ex2f(a2);
        // inside = 1 / ((1+e0)(1+e1)(1+e2))
        float t12 = (1.0f + e1) * (1.0f + e2);
        float P   = fmaf(e0, t12, t12);
        float arg = (1.0f - rcpaf(P)) + 1e-7f;   // same rounding as reference
        acc += lg2af(arg);
    }

    g_lm[g][h * WW + w] = fmaf((float)nskip, SKIP_CONST, acc);
}

// ---------------------------------------------------------------------------
// K2: image + squared-diff partial sums per pixel block
// ---------------------------------------------------------------------------
__global__ void __launch_bounds__(256) image_kernel(const float* __restrict__ ref)
{
    int p = blockIdx.x * 256 + threadIdx.x;
    float lm = g_lm[0][p] + g_lm[1][p] + g_lm[2][p] + g_lm[3][p];
    float img = 1.0f - ex2f(lm);
    float d = ref[p] - img;
    float v = d * d;

    #pragma unroll
    for (int off = 16; off; off >>= 1)
        v += __shfl_xor_sync(0xffffffffu, v, off);

    __shared__ float ws[8];
    if ((threadIdx.x & 31) == 0) ws[threadIdx.x >> 5] = v;
    __syncthreads();
    if (threadIdx.x == 0) {
        float s = 0.0f;
        #pragma unroll
        for (int i = 0; i < 8; i++) s += ws[i];
        g_partial[blockIdx.x] = s;
    }
}

// ---------------------------------------------------------------------------
// K3: final reduction + distance penalty
// ---------------------------------------------------------------------------
__global__ void __launch_bounds__(256) loss_kernel(const float* __restrict__ cam,
                                                   float* __restrict__ out)
{
    __shared__ float ws[8];
    int tid = threadIdx.x;
    float v = (tid < PIX_BLOCKS) ? g_partial[tid] : 0.0f;

    #pragma unroll
    for (int off = 16; off; off >>= 1)
        v += __shfl_xor_sync(0xffffffffu, v, off);
    if ((tid & 31) == 0) ws[tid >> 5] = v;
    __syncthreads();

    if (tid == 0) {
        float s = 0.0f;
        #pragma unroll
        for (int i = 0; i < 8; i++) s += ws[i];
        float dx = cam[0], dy = cam[1], dz = cam[2];
        float dist = sqrtf(dx * dx + dy * dy + dz * dz);
        float pen = fmaxf(6.0f - dist, 0.0f);
        out[0] = s * (1.0f + pen);
    }
}

// ---------------------------------------------------------------------------
extern "C" void kernel_launch(void* const* d_in, const int* in_sizes, int n_in,
                              void* d_out, int out_size)
{
    const float* verts = (const float*)d_in[0];
    const int*   faces = (const int*)d_in[1];
    const float* ref   = (const float*)d_in[2];
    const float* cam   = (const float*)d_in[3];
    float* out = (float*)d_out;
    (void)in_sizes; (void)n_in; (void)out_size;

    setup_kernel<<<1, 1024>>>(verts, faces, cam);
    bin_kernel<<<NTILE, 256>>>();
    dim3 grid(NTILE, G);
    face_kernel<<<grid, 256>>>();
    image_kernel<<<PIX_BLOCKS, 256>>>(ref);
    loss_kernel<<<1, 256>>>(cam, out);
}